// round 4
// baseline (speedup 1.0000x reference)
#include <cuda_runtime.h>
#include <cuda_fp16.h>

#define NN 25000
#define NE 400000
#define EE (NE + NN)          // 425000 (edges + self loops)
#define SC 0.35355339059327378f   // 1/sqrt(8)

// ---------------- scratch (static __device__, no allocs) ----------------
__device__ float2   g_x0[NN * 32];   // layer-0 h, pair layout (lane l = dims 2l,2l+1)
__device__ float2   g_x1[NN * 32];   // layer-1 out
__device__ float2   g_QA[NN * 32];   // Q after layer1 (pre-scaled by SC)
__device__ float2   g_QB[NN * 32];   // Q after layer2
__device__ unsigned g_V1[NN * 32];   // layer-0 V half2 (unscaled)
__device__ uint4    g_KVA[NN * 32];  // {K_l0, V_l0*dis, K_l1, V_l1*dis} (layer-1 weights)
__device__ uint4    g_KVB[NN * 32];  // {K_l0, V_l0*dis, K_l1, V_l1*dis} (layer-2 weights)
__device__ uint2    g_KVc[NN * 32];  // {K_l2, V_l2*dis} (layer-2 weights)
__device__ float    g_dis[NN];
__device__ int      g_deg[NN];       // invariant: all-zero at kernel_launch entry
__device__ int      g_off[NN + 1];
__device__ int      g_cur[NN];
__device__ int      g_csr[EE];

__device__ __forceinline__ float2 u2f(unsigned u) {
    return __half22float2(*reinterpret_cast<const __half2*>(&u));
}
__device__ __forceinline__ unsigned f2u(float x, float y) {
    __half2 h = __floats2half2_rn(x, y);
    return *reinterpret_cast<unsigned*>(&h);
}

// ---------------- CSR build ----------------
__global__ void k_hist(const int* __restrict__ ei) {
    int e = blockIdx.x * blockDim.x + threadIdx.x;
    if (e < NE) atomicAdd(&g_deg[ei[NE + e]], 1);   // col = ei[1]; self loop is implicit +1
}

// single-block scan over NN elements; also computes dis, seeds cur, resets deg
__global__ void k_scan() {
    __shared__ int wsum[32];
    int t = threadIdx.x;
    int lane = t & 31, wid = t >> 5;
    int i0 = t * 25;
    int i1 = i0 + 25 < NN ? i0 + 25 : NN;
    int s = 0;
    for (int i = i0; i < i1; i++) s += g_deg[i] + 1;   // +1 = self loop
    int inc = s;
#pragma unroll
    for (int o = 1; o < 32; o <<= 1) {
        int v = __shfl_up_sync(0xffffffffu, inc, o);
        if (lane >= o) inc += v;
    }
    if (lane == 31) wsum[wid] = inc;
    __syncthreads();
    if (t < 32) {
        int v = wsum[t];
        int inc2 = v;
#pragma unroll
        for (int o = 1; o < 32; o <<= 1) {
            int u = __shfl_up_sync(0xffffffffu, inc2, o);
            if (t >= o) inc2 += u;
        }
        wsum[t] = inc2 - v;   // exclusive
    }
    __syncthreads();
    int run = wsum[wid] + (inc - s);
    for (int i = i0; i < i1; i++) {
        int d = g_deg[i] + 1;
        g_off[i] = run;
        g_cur[i] = run;
        g_dis[i] = rsqrtf((float)d);
        g_deg[i] = 0;          // restore invariant for next replay
        run += d;
    }
    if (t == 0) g_off[NN] = EE;
}

__global__ void k_scatter(const int* __restrict__ ei) {
    int idx = blockIdx.x * blockDim.x + threadIdx.x;
    if (idx >= EE) return;
    int r, c;
    if (idx < NE) { r = ei[idx]; c = ei[NE + idx]; }
    else          { r = c = idx - NE; }               // self loop
    int p = atomicAdd(&g_cur[c], 1);
    g_csr[p] = r;
}

// ---------------- helpers ----------------
// gather this lane's group inputs x[g0*8+i] from warp-held pair registers
__device__ __forceinline__ void gather_pair(float2 h, int g0, float (&xa)[8]) {
#pragma unroll
    for (int i = 0; i < 8; i += 2) {
        int src = g0 * 4 + (i >> 1);
        xa[i]     = __shfl_sync(0xffffffffu, h.x, src);
        xa[i + 1] = __shfl_sync(0xffffffffu, h.y, src);
    }
}

// [8][8][8] weights into padded smem (stride 33 float2 per group)
__device__ __forceinline__ void load_w_padded(const float* __restrict__ w, float2* sw) {
    for (int i = threadIdx.x; i < 256; i += blockDim.x) {
        int g = i >> 5, r = i & 31;
        sw[g * 33 + r] = ((const float2*)w)[i];
    }
}

__device__ __forceinline__ float2 glin(const float2* sw, const float* sb,
                                       const float (&xa)[8], int wbase, int lane) {
    float2 o = ((const float2*)sb)[lane];
#pragma unroll
    for (int i = 0; i < 8; i++) {
        float2 w = sw[wbase + i * 4];
        o.x += xa[i] * w.x;
        o.y += xa[i] * w.y;
    }
    return o;
}

// ---------------- fused lin1 + qkv1(V only) ----------------
// warp handles 8 nodes; lane covers dims {2*lane, 2*lane+1}
__global__ void k_lin1qkv1(const float* __restrict__ x, const float* __restrict__ w,
                           const float* __restrict__ b,
                           const float* __restrict__ wv0, const float* __restrict__ bv0) {
    __shared__ float2 swv[264];
    __shared__ float sbv[64];
    load_w_padded(wv0, swv);
    if (threadIdx.x < 64) sbv[threadIdx.x] = bv0[threadIdx.x];
    __syncthreads();
    int gw = (blockIdx.x * blockDim.x + threadIdx.x) >> 5;
    int lane = threadIdx.x & 31;
    int base = gw * 8;                 // NN % 8 == 0
    if (base >= NN) return;
    const float2* W2 = (const float2*)w;   // [256][32] float2
    float2 acc[8];
#pragma unroll
    for (int n = 0; n < 8; n++) acc[n] = make_float2(0.f, 0.f);
    for (int k0 = 0; k0 < 256; k0 += 32) {
        float xr[8];
#pragma unroll
        for (int n = 0; n < 8; n++) xr[n] = x[(base + n) * 256 + k0 + lane];
#pragma unroll
        for (int kk = 0; kk < 32; kk++) {
            float2 wv = W2[(k0 + kk) * 32 + lane];
#pragma unroll
            for (int n = 0; n < 8; n++) {
                float bv = __shfl_sync(0xffffffffu, xr[n], kk);
                acc[n].x += bv * wv.x;
                acc[n].y += bv * wv.y;
            }
        }
    }
    float2 bb = ((const float2*)b)[lane];
    int g0 = lane >> 2;
    int wbase = g0 * 33 + (lane & 3);
#pragma unroll
    for (int n = 0; n < 8; n++) {
        float2 h = make_float2(fmaxf(acc[n].x + bb.x, 0.f), fmaxf(acc[n].y + bb.y, 0.f));
        g_x0[(base + n) * 32 + lane] = h;
        float xa[8];
        gather_pair(h, g0, xa);
        float2 vv = glin(swv, sbv, xa, wbase, lane);
        g_V1[(base + n) * 32 + lane] = f2u(vv.x, vv.y);   // unscaled; dis applied in edge1
    }
}

// ---------------- fused edge1 (identity attention) + qkv2 ----------------
__global__ void k_edge1qkv2(const float* __restrict__ wq, const float* __restrict__ bq,
                            const float* __restrict__ wk, const float* __restrict__ bk,
                            const float* __restrict__ wv, const float* __restrict__ bv) {
    __shared__ float2 swq[264], swk[264], swv[264];
    __shared__ float sbq[64], sbk[64], sbv[64];
    load_w_padded(wq, swq);
    load_w_padded(wk, swk);
    load_w_padded(wv, swv);
    if (threadIdx.x < 64) {
        sbq[threadIdx.x] = bq[threadIdx.x];
        sbk[threadIdx.x] = bk[threadIdx.x];
        sbv[threadIdx.x] = bv[threadIdx.x];
    }
    __syncthreads();
    int c = (blockIdx.x * blockDim.x + threadIdx.x) >> 5;
    if (c >= NN) return;
    int lane = threadIdx.x & 31;
    float ax = 0.f, ay = 0.f;
    int j = g_off[c], end = g_off[c + 1];
    for (; j + 4 <= end; j += 4) {
        int r0 = __ldg(&g_csr[j]), r1 = __ldg(&g_csr[j + 1]);
        int r2 = __ldg(&g_csr[j + 2]), r3 = __ldg(&g_csr[j + 3]);
        unsigned u0 = __ldg(&g_V1[r0 * 32 + lane]);
        unsigned u1 = __ldg(&g_V1[r1 * 32 + lane]);
        unsigned u2 = __ldg(&g_V1[r2 * 32 + lane]);
        unsigned u3 = __ldg(&g_V1[r3 * 32 + lane]);
        float d0 = __ldg(&g_dis[r0]), d1 = __ldg(&g_dis[r1]);
        float d2 = __ldg(&g_dis[r2]), d3 = __ldg(&g_dis[r3]);
        float2 f0 = u2f(u0), f1 = u2f(u1), f2 = u2f(u2), f3 = u2f(u3);
        ax += d0 * f0.x + d1 * f1.x + d2 * f2.x + d3 * f3.x;
        ay += d0 * f0.y + d1 * f1.y + d2 * f2.y + d3 * f3.y;
    }
    for (; j < end; j++) {
        int r = __ldg(&g_csr[j]);
        float2 f = u2f(__ldg(&g_V1[r * 32 + lane]));
        float dr = __ldg(&g_dis[r]);
        ax += dr * f.x;  ay += dr * f.y;
    }
    float dc = g_dis[c];
    float2 h1 = make_float2(fmaxf(ax * dc, 0.f), fmaxf(ay * dc, 0.f));
    g_x1[c * 32 + lane] = h1;

    // qkv2: layers {0,1} K,V + Q(layer1), with net-layer-1 weights
    int g0 = lane >> 2;
    int wbase = g0 * 33 + (lane & 3);
    float2 h0 = g_x0[c * 32 + lane];
    float xa[8];
    uint4 pack;
    gather_pair(h0, g0, xa);
    {
        float2 kk = glin(swk, sbk, xa, wbase, lane);
        float2 vv = glin(swv, sbv, xa, wbase, lane);
        pack.x = f2u(kk.x, kk.y);
        pack.y = f2u(vv.x * dc, vv.y * dc);
    }
    gather_pair(h1, g0, xa);
    {
        float2 kk = glin(swk, sbk, xa, wbase, lane);
        float2 vv = glin(swv, sbv, xa, wbase, lane);
        float2 qq = glin(swq, sbq, xa, wbase, lane);
        pack.z = f2u(kk.x, kk.y);
        pack.w = f2u(vv.x * dc, vv.y * dc);
        g_QA[c * 32 + lane] = make_float2(qq.x * SC, qq.y * SC);
    }
    g_KVA[c * 32 + lane] = pack;
}

// ---------------- attention accumulators ----------------
__device__ __forceinline__ void acc2(uint4 d, float2 qv, float& ax, float& ay) {
    float2 k0 = u2f(d.x), v0 = u2f(d.y), k1 = u2f(d.z), v1 = u2f(d.w);
    float s0 = qv.x * k0.x + qv.y * k0.y;
    s0 += __shfl_xor_sync(0xffffffffu, s0, 1);
    s0 += __shfl_xor_sync(0xffffffffu, s0, 2);
    float s1 = qv.x * k1.x + qv.y * k1.y;
    s1 += __shfl_xor_sync(0xffffffffu, s1, 1);
    s1 += __shfl_xor_sync(0xffffffffu, s1, 2);
    float m = fmaxf(s0, s1);
    float e0 = __expf(s0 - m), e1 = __expf(s1 - m);
    float inv = __fdividef(1.0f, e0 + e1);
    ax += (e0 * v0.x + e1 * v1.x) * inv;
    ay += (e0 * v0.y + e1 * v1.y) * inv;
}

__device__ __forceinline__ void acc3(uint4 d, uint2 e, float2 qv, float& ax, float& ay) {
    float2 k0 = u2f(d.x), v0 = u2f(d.y), k1 = u2f(d.z), v1 = u2f(d.w);
    float2 k2 = u2f(e.x), v2 = u2f(e.y);
    float s0 = qv.x * k0.x + qv.y * k0.y;
    s0 += __shfl_xor_sync(0xffffffffu, s0, 1);
    s0 += __shfl_xor_sync(0xffffffffu, s0, 2);
    float s1 = qv.x * k1.x + qv.y * k1.y;
    s1 += __shfl_xor_sync(0xffffffffu, s1, 1);
    s1 += __shfl_xor_sync(0xffffffffu, s1, 2);
    float s2 = qv.x * k2.x + qv.y * k2.y;
    s2 += __shfl_xor_sync(0xffffffffu, s2, 1);
    s2 += __shfl_xor_sync(0xffffffffu, s2, 2);
    float m = fmaxf(fmaxf(s0, s1), s2);
    float e0 = __expf(s0 - m), e1 = __expf(s1 - m), e2 = __expf(s2 - m);
    float inv = __fdividef(1.0f, e0 + e1 + e2);
    ax += (e0 * v0.x + e1 * v1.x + e2 * v2.x) * inv;
    ay += (e0 * v0.y + e1 * v1.y + e2 * v2.y) * inv;
}

// ---------------- fused edge2 + qkv3 ----------------
__global__ void k_edge2qkv3(const float* __restrict__ wq, const float* __restrict__ bq,
                            const float* __restrict__ wk, const float* __restrict__ bk,
                            const float* __restrict__ wv, const float* __restrict__ bv) {
    __shared__ float2 swq[264], swk[264], swv[264];
    __shared__ float sbq[64], sbk[64], sbv[64];
    load_w_padded(wq, swq);
    load_w_padded(wk, swk);
    load_w_padded(wv, swv);
    if (threadIdx.x < 64) {
        sbq[threadIdx.x] = bq[threadIdx.x];
        sbk[threadIdx.x] = bk[threadIdx.x];
        sbv[threadIdx.x] = bv[threadIdx.x];
    }
    __syncthreads();
    int c = (blockIdx.x * blockDim.x + threadIdx.x) >> 5;
    if (c >= NN) return;
    int lane = threadIdx.x & 31;
    float2 qv = g_QA[c * 32 + lane];
    float ax = 0.f, ay = 0.f;
    int j = g_off[c], end = g_off[c + 1];
    for (; j + 4 <= end; j += 4) {
        int r0 = __ldg(&g_csr[j]), r1 = __ldg(&g_csr[j + 1]);
        int r2 = __ldg(&g_csr[j + 2]), r3 = __ldg(&g_csr[j + 3]);
        uint4 d0 = __ldg(&g_KVA[r0 * 32 + lane]);
        uint4 d1 = __ldg(&g_KVA[r1 * 32 + lane]);
        uint4 d2 = __ldg(&g_KVA[r2 * 32 + lane]);
        uint4 d3 = __ldg(&g_KVA[r3 * 32 + lane]);
        acc2(d0, qv, ax, ay);
        acc2(d1, qv, ax, ay);
        acc2(d2, qv, ax, ay);
        acc2(d3, qv, ax, ay);
    }
    for (; j < end; j++)
        acc2(__ldg(&g_KVA[__ldg(&g_csr[j]) * 32 + lane]), qv, ax, ay);

    float dc = g_dis[c];
    float2 h2 = make_float2(fmaxf(ax * dc, 0.f), fmaxf(ay * dc, 0.f));
    // (x_all layer-2 not stored: only consumed here in registers)

    // qkv3: layers {0,1,2} K,V + Q(layer2), with net-layer-2 weights
    int g0 = lane >> 2;
    int wbase = g0 * 33 + (lane & 3);
    float xa[8];
    uint4 packA;
    gather_pair(g_x0[c * 32 + lane], g0, xa);
    {
        float2 kk = glin(swk, sbk, xa, wbase, lane);
        float2 vv = glin(swv, sbv, xa, wbase, lane);
        packA.x = f2u(kk.x, kk.y);
        packA.y = f2u(vv.x * dc, vv.y * dc);
    }
    gather_pair(g_x1[c * 32 + lane], g0, xa);
    {
        float2 kk = glin(swk, sbk, xa, wbase, lane);
        float2 vv = glin(swv, sbv, xa, wbase, lane);
        packA.z = f2u(kk.x, kk.y);
        packA.w = f2u(vv.x * dc, vv.y * dc);
    }
    g_KVB[c * 32 + lane] = packA;
    gather_pair(h2, g0, xa);
    {
        float2 kk = glin(swk, sbk, xa, wbase, lane);
        float2 vv = glin(swv, sbv, xa, wbase, lane);
        float2 qq = glin(swq, sbq, xa, wbase, lane);
        g_KVc[c * 32 + lane] = make_uint2(f2u(kk.x, kk.y), f2u(vv.x * dc, vv.y * dc));
        g_QB[c * 32 + lane] = make_float2(qq.x * SC, qq.y * SC);
    }
}

// ---------------- fused edge3 + lin2 + log_softmax ----------------
__global__ void k_edge3lin2(const float* __restrict__ w, const float* __restrict__ b,
                            float* __restrict__ out) {
    __shared__ float sw[2048];   // [64][32]
    __shared__ float sb[32];
    for (int i = threadIdx.x; i < 2048; i += blockDim.x) sw[i] = w[i];
    if (threadIdx.x < 32) sb[threadIdx.x] = b[threadIdx.x];
    __syncthreads();
    int c = (blockIdx.x * blockDim.x + threadIdx.x) >> 5;
    if (c >= NN) return;
    int lane = threadIdx.x & 31;
    float2 qv = g_QB[c * 32 + lane];
    float ax = 0.f, ay = 0.f;
    int j = g_off[c], end = g_off[c + 1];
    for (; j + 4 <= end; j += 4) {
        int r0 = __ldg(&g_csr[j]), r1 = __ldg(&g_csr[j + 1]);
        int r2 = __ldg(&g_csr[j + 2]), r3 = __ldg(&g_csr[j + 3]);
        uint4 d0 = __ldg(&g_KVB[r0 * 32 + lane]);
        uint4 d1 = __ldg(&g_KVB[r1 * 32 + lane]);
        uint4 d2 = __ldg(&g_KVB[r2 * 32 + lane]);
        uint4 d3 = __ldg(&g_KVB[r3 * 32 + lane]);
        uint2 e0 = __ldg(&g_KVc[r0 * 32 + lane]);
        uint2 e1 = __ldg(&g_KVc[r1 * 32 + lane]);
        uint2 e2 = __ldg(&g_KVc[r2 * 32 + lane]);
        uint2 e3 = __ldg(&g_KVc[r3 * 32 + lane]);
        acc3(d0, e0, qv, ax, ay);
        acc3(d1, e1, qv, ax, ay);
        acc3(d2, e2, qv, ax, ay);
        acc3(d3, e3, qv, ax, ay);
    }
    for (; j < end; j++) {
        int r = __ldg(&g_csr[j]);
        acc3(__ldg(&g_KVB[r * 32 + lane]), __ldg(&g_KVc[r * 32 + lane]), qv, ax, ay);
    }
    float dc = g_dis[c];
    float hx = fmaxf(ax * dc, 0.f), hy = fmaxf(ay * dc, 0.f);

    // lin2: lane = class
    float acc = sb[lane];
#pragma unroll
    for (int lp = 0; lp < 32; lp++) {
        float bx = __shfl_sync(0xffffffffu, hx, lp);
        float by = __shfl_sync(0xffffffffu, hy, lp);
        acc += bx * sw[(2 * lp) * 32 + lane] + by * sw[(2 * lp + 1) * 32 + lane];
    }
    float m = acc;
#pragma unroll
    for (int o = 16; o; o >>= 1) m = fmaxf(m, __shfl_xor_sync(0xffffffffu, m, o));
    float e = __expf(acc - m);
    float sum = e;
#pragma unroll
    for (int o = 16; o; o >>= 1) sum += __shfl_xor_sync(0xffffffffu, sum, o);
    out[(size_t)c * 32 + lane] = acc - m - logf(sum);
}

// ---------------- launch ----------------
extern "C" void kernel_launch(void* const* d_in, const int* in_sizes, int n_in,
                              void* d_out, int out_size) {
    const float* x  = (const float*)d_in[0];
    const int*   ei = (const int*)d_in[1];
    const float* w1 = (const float*)d_in[2];
    const float* b1 = (const float*)d_in[3];
    const float* wq = (const float*)d_in[4];
    const float* bq = (const float*)d_in[5];
    const float* wk = (const float*)d_in[6];
    const float* bk = (const float*)d_in[7];
    const float* wv = (const float*)d_in[8];
    const float* bv = (const float*)d_in[9];
    const float* w2 = (const float*)d_in[10];
    const float* b2 = (const float*)d_in[11];
    float* out = (float*)d_out;

    // statics created on the (uncaptured) correctness call; reused during capture
    static cudaStream_t s2 = nullptr;
    static cudaEvent_t evA = nullptr, evB = nullptr;
    static bool init_done = false;
    if (!init_done) {
        if (cudaStreamCreateWithFlags(&s2, cudaStreamNonBlocking) != cudaSuccess) s2 = nullptr;
        if (cudaEventCreateWithFlags(&evA, cudaEventDisableTiming) != cudaSuccess) evA = nullptr;
        if (cudaEventCreateWithFlags(&evB, cudaEventDisableTiming) != cudaSuccess) evB = nullptr;
        init_done = true;
    }
    bool fork = (s2 != nullptr && evA != nullptr && evB != nullptr);

    const int gridW = (NN * 32 + 255) / 256;            // warp-per-node kernels
    const int gridL1 = ((NN / 8) * 32 + 255) / 256;     // 8 nodes per warp

    if (fork) {
        cudaEventRecord(evA, 0);
        cudaStreamWaitEvent(s2, evA, 0);
        k_lin1qkv1<<<gridL1, 256, 0, s2>>>(x, w1, b1, wv, bv);
        cudaEventRecord(evB, s2);
    } else {
        k_lin1qkv1<<<gridL1, 256>>>(x, w1, b1, wv, bv);
    }

    // CSR + norm (concurrent with lin1qkv1)
    k_hist<<<(NE + 255) / 256, 256>>>(ei);
    k_scan<<<1, 1024>>>();
    k_scatter<<<(EE + 255) / 256, 256>>>(ei);

    if (fork) cudaStreamWaitEvent(0, evB, 0);

    k_edge1qkv2<<<gridW, 256>>>(wq + 512, bq + 64, wk + 512, bk + 64, wv + 512, bv + 64);
    k_edge2qkv3<<<gridW, 256>>>(wq + 1024, bq + 128, wk + 1024, bk + 128, wv + 1024, bv + 128);
    k_edge3lin2<<<gridW, 256>>>(w2, b2, out);
}